// round 1
// baseline (speedup 1.0000x reference)
#include <cuda_runtime.h>
#include <math.h>

// ---------------- problem constants ----------------
#define Bb 4
#define Ss 2048
#define Dd 1024
#define CTX 77
#define CTXD 768
#define Hh 16
#define DH 64
#define INNER 1024
#define FF 4096      // D*MULT
#define FF2 8192     // D*MULT*2
#define MX (Bb*Ss)   // 8192 rows of the main stream

// ---------------- scratch (static device globals; no allocs) ----------------
__device__ float g_xn[MX * Dd];                    // layernorm output (reused x3)
__device__ float g_q [MX * INNER];
__device__ float g_k [MX * INNER];                 // also holds cross K2 [B,77,INNER]
__device__ float g_v [MX * INNER];                 // also holds cross V2
__device__ float g_ao[MX * INNER];                 // attention output (pre o-proj)
__device__ float g_x1[MX * Dd];                    // residual stream
__device__ float g_sc[(long)Bb * Hh * Ss * Ss];    // scores (1 GiB; reused for cross)
__device__ float g_ff[(long)MX * FF2];             // FF1 output (256 MB)
__device__ float g_gg[(long)MX * FF];              // geglu output (128 MB)

// ---------------- reductions ----------------
__device__ __forceinline__ float warp_sum(float v) {
    #pragma unroll
    for (int o = 16; o > 0; o >>= 1) v += __shfl_xor_sync(0xffffffffu, v, o);
    return v;
}
__device__ __forceinline__ float warp_max(float v) {
    #pragma unroll
    for (int o = 16; o > 0; o >>= 1) v = fmaxf(v, __shfl_xor_sync(0xffffffffu, v, o));
    return v;
}

// ---------------- layernorm: one block per row, D=1024 ----------------
__global__ void ln_kernel(const float* __restrict__ x, const float* __restrict__ g,
                          const float* __restrict__ b, float* __restrict__ y) {
    long row = blockIdx.x;
    const float* xr = x + row * Dd;
    float s = 0.f, s2 = 0.f;
    for (int i = threadIdx.x; i < Dd; i += blockDim.x) {
        float v = xr[i];
        s += v; s2 += v * v;
    }
    __shared__ float sm1[32], sm2[32];
    s = warp_sum(s); s2 = warp_sum(s2);
    int lane = threadIdx.x & 31, w = threadIdx.x >> 5;
    if (lane == 0) { sm1[w] = s; sm2[w] = s2; }
    __syncthreads();
    int nw = blockDim.x >> 5;
    if (w == 0) {
        float a = (lane < nw) ? sm1[lane] : 0.f;
        float c = (lane < nw) ? sm2[lane] : 0.f;
        a = warp_sum(a); c = warp_sum(c);
        if (lane == 0) { sm1[0] = a; sm2[0] = c; }
    }
    __syncthreads();
    float mu = sm1[0] * (1.f / Dd);
    float var = sm2[0] * (1.f / Dd) - mu * mu;
    float inv = rsqrtf(var + 1e-5f);
    float* yr = y + row * Dd;
    for (int i = threadIdx.x; i < Dd; i += blockDim.x)
        yr[i] = (xr[i] - mu) * inv * g[i] + b[i];
}

// ---------------- generic tiled GEMM (128x128x8, 8x8 microtile) ----------------
// C[m,n] = alpha * sum_k A[m,k]*B'[k,n]  (+bias[n]) (+res[m,n])
// TB=false: B row-major [K,N]; TB=true: B row-major [N,K] (i.e. C = A * B^T)
// Batch: blockIdx.z = z; zb=z/HH, zh=z%HH; ptr += zb*s?b + zh*s?h
template <bool TB>
__global__ void gemm_kernel(const float* __restrict__ A, const float* __restrict__ B,
                            float* __restrict__ C,
                            int M, int N, int K, int lda, int ldb, int ldc,
                            long sAb, long sAh, long sBb, long sBh, long sCb, long sCh,
                            int HH, float alpha,
                            const float* __restrict__ bias,
                            const float* __restrict__ res, long sRb, long sRh, int ldr) {
    __shared__ float As[8][128];
    __shared__ float Bs[8][128];
    int z = blockIdx.z;
    int zb = z / HH, zh = z % HH;
    A += zb * sAb + zh * sAh;
    B += zb * sBb + zh * sBh;
    C += zb * sCb + zh * sCh;
    if (res) res += zb * sRb + zh * sRh;

    int m0 = blockIdx.y * 128;
    int n0 = blockIdx.x * 128;
    int tid = threadIdx.x;
    int tx = tid & 15, ty = tid >> 4;

    float acc[8][8];
    #pragma unroll
    for (int i = 0; i < 8; i++)
        #pragma unroll
        for (int j = 0; j < 8; j++) acc[i][j] = 0.f;

    for (int k0 = 0; k0 < K; k0 += 8) {
        #pragma unroll
        for (int i = 0; i < 4; i++) {
            int e = tid + i * 256;          // 0..1023
            int r = e >> 3, c = e & 7;      // A tile: 128 rows x 8 k
            int gm = m0 + r, gk = k0 + c;
            float v = 0.f;
            if (gm < M && gk < K) v = A[(long)gm * lda + gk];
            As[c][r] = v;
        }
        #pragma unroll
        for (int i = 0; i < 4; i++) {
            int e = tid + i * 256;
            int kk = e >> 7, n = e & 127;   // B tile: 8 k x 128 n
            int gn = n0 + n, gk = k0 + kk;
            float v = 0.f;
            if (gn < N && gk < K)
                v = TB ? B[(long)gn * ldb + gk] : B[(long)gk * ldb + gn];
            Bs[kk][n] = v;
        }
        __syncthreads();
        #pragma unroll
        for (int kk = 0; kk < 8; kk++) {
            float a[8], bb[8];
            #pragma unroll
            for (int i = 0; i < 8; i++) a[i] = As[kk][ty * 8 + i];
            #pragma unroll
            for (int j = 0; j < 8; j++) bb[j] = Bs[kk][tx * 8 + j];
            #pragma unroll
            for (int i = 0; i < 8; i++)
                #pragma unroll
                for (int j = 0; j < 8; j++) acc[i][j] += a[i] * bb[j];
        }
        __syncthreads();
    }

    #pragma unroll
    for (int i = 0; i < 8; i++) {
        int gm = m0 + ty * 8 + i;
        if (gm >= M) continue;
        #pragma unroll
        for (int j = 0; j < 8; j++) {
            int gn = n0 + tx * 8 + j;
            if (gn >= N) continue;
            float v = acc[i][j] * alpha;
            if (bias) v += bias[gn];
            if (res)  v += res[(long)gm * ldr + gn];
            C[(long)gm * ldc + gn] = v;
        }
    }
}

// ---------------- row softmax (in place) ----------------
__global__ void softmax_kernel(float* __restrict__ p, int L) {
    long row = blockIdx.x;
    float* r = p + row * (long)L;
    float mx = -INFINITY;
    for (int i = threadIdx.x; i < L; i += blockDim.x) mx = fmaxf(mx, r[i]);
    __shared__ float sm[32];
    mx = warp_max(mx);
    int lane = threadIdx.x & 31, w = threadIdx.x >> 5;
    int nw = blockDim.x >> 5;
    if (lane == 0) sm[w] = mx;
    __syncthreads();
    if (w == 0) {
        float v = (lane < nw) ? sm[lane] : -INFINITY;
        v = warp_max(v);
        if (lane == 0) sm[0] = v;
    }
    __syncthreads();
    mx = sm[0];
    __syncthreads();
    float s = 0.f;
    for (int i = threadIdx.x; i < L; i += blockDim.x) {
        float e = __expf(r[i] - mx);
        r[i] = e;
        s += e;
    }
    s = warp_sum(s);
    if (lane == 0) sm[w] = s;
    __syncthreads();
    if (w == 0) {
        float v = (lane < nw) ? sm[lane] : 0.f;
        v = warp_sum(v);
        if (lane == 0) sm[0] = v;
    }
    __syncthreads();
    float inv = 1.f / sm[0];
    for (int i = threadIdx.x; i < L; i += blockDim.x) r[i] *= inv;
}

// ---------------- GeGLU: out[m,n] = u * gelu_exact(gate) ----------------
__global__ void geglu_kernel(const float* __restrict__ h, float* __restrict__ o) {
    long idx = (long)blockIdx.x * blockDim.x + threadIdx.x;
    long total = (long)MX * FF;
    if (idx >= total) return;
    long m = idx / FF;
    int  n = (int)(idx - m * FF);
    float u    = h[m * FF2 + n];
    float gate = h[m * FF2 + FF + n];
    float ge = 0.5f * gate * (1.f + erff(gate * 0.70710678118654752f));
    o[idx] = u * ge;
}

// ---------------- launch helper ----------------
static void run_gemm(bool tb, const float* A, const float* B, float* C,
                     int M, int N, int K, int lda, int ldb, int ldc,
                     long sAb, long sAh, long sBb, long sBh, long sCb, long sCh,
                     int HH, int Z, float alpha,
                     const float* bias, const float* res, long sRb, long sRh, int ldr) {
    dim3 grid((N + 127) / 128, (M + 127) / 128, Z);
    if (tb)
        gemm_kernel<true><<<grid, 256>>>(A, B, C, M, N, K, lda, ldb, ldc,
                                         sAb, sAh, sBb, sBh, sCb, sCh, HH, alpha,
                                         bias, res, sRb, sRh, ldr);
    else
        gemm_kernel<false><<<grid, 256>>>(A, B, C, M, N, K, lda, ldb, ldc,
                                          sAb, sAh, sBb, sBh, sCb, sCh, HH, alpha,
                                          bias, res, sRb, sRh, ldr);
}

extern "C" void kernel_launch(void* const* d_in, const int* in_sizes, int n_in,
                              void* d_out, int out_size) {
    const float* x      = (const float*)d_in[0];
    const float* ctx    = (const float*)d_in[1];
    const float* ln1_g  = (const float*)d_in[2];
    const float* ln1_b  = (const float*)d_in[3];
    const float* ln2_g  = (const float*)d_in[4];
    const float* ln2_b  = (const float*)d_in[5];
    const float* ln3_g  = (const float*)d_in[6];
    const float* ln3_b  = (const float*)d_in[7];
    const float* a1_wq  = (const float*)d_in[8];
    const float* a1_wk  = (const float*)d_in[9];
    const float* a1_wv  = (const float*)d_in[10];
    const float* a1_wo  = (const float*)d_in[11];
    const float* a1_bo  = (const float*)d_in[12];
    const float* a2_wq  = (const float*)d_in[13];
    const float* a2_wk  = (const float*)d_in[14];
    const float* a2_wv  = (const float*)d_in[15];
    const float* a2_wo  = (const float*)d_in[16];
    const float* a2_bo  = (const float*)d_in[17];
    const float* ff_w1  = (const float*)d_in[18];
    const float* ff_b1  = (const float*)d_in[19];
    const float* ff_w2  = (const float*)d_in[20];
    const float* ff_b2  = (const float*)d_in[21];
    float* out = (float*)d_out;

    float *xn, *q, *k, *v, *ao, *x1, *sc, *ff, *gg;
    cudaGetSymbolAddress((void**)&xn, g_xn);
    cudaGetSymbolAddress((void**)&q,  g_q);
    cudaGetSymbolAddress((void**)&k,  g_k);
    cudaGetSymbolAddress((void**)&v,  g_v);
    cudaGetSymbolAddress((void**)&ao, g_ao);
    cudaGetSymbolAddress((void**)&x1, g_x1);
    cudaGetSymbolAddress((void**)&sc, g_sc);
    cudaGetSymbolAddress((void**)&ff, g_ff);
    cudaGetSymbolAddress((void**)&gg, g_gg);

    const float scale = 0.125f;  // DH^-0.5

    // ===== self-attention =====
    ln_kernel<<<MX, 256>>>(x, ln1_g, ln1_b, xn);
    run_gemm(false, xn, a1_wq, q, MX, INNER, Dd, Dd, INNER, INNER,
             0,0,0,0,0,0, 1, 1, 1.f, nullptr, nullptr, 0,0,0);
    run_gemm(false, xn, a1_wk, k, MX, INNER, Dd, Dd, INNER, INNER,
             0,0,0,0,0,0, 1, 1, 1.f, nullptr, nullptr, 0,0,0);
    run_gemm(false, xn, a1_wv, v, MX, INNER, Dd, Dd, INNER, INNER,
             0,0,0,0,0,0, 1, 1, 1.f, nullptr, nullptr, 0,0,0);
    // scores[z=(b,h)] = Q_slice @ K_slice^T * scale   (M=S, N=S, K=DH)
    run_gemm(true, q, k, sc, Ss, Ss, DH, INNER, INNER, Ss,
             (long)Ss*INNER, DH, (long)Ss*INNER, DH,
             (long)Hh*Ss*Ss, (long)Ss*Ss, Hh, Bb*Hh, scale,
             nullptr, nullptr, 0,0,0);
    softmax_kernel<<<(long)Bb*Hh*Ss, 256>>>(sc, Ss);
    // attn_out[z] = P @ V_slice   (M=S, N=DH, K=S)
    run_gemm(false, sc, v, ao, Ss, DH, Ss, Ss, INNER, INNER,
             (long)Hh*Ss*Ss, (long)Ss*Ss, (long)Ss*INNER, DH,
             (long)Ss*INNER, DH, Hh, Bb*Hh, 1.f,
             nullptr, nullptr, 0,0,0);
    // x1 = ao @ a1_wo + a1_bo + x
    run_gemm(false, ao, a1_wo, x1, MX, Dd, INNER, INNER, Dd, Dd,
             0,0,0,0,0,0, 1, 1, 1.f, a1_bo, x, 0,0, Dd);

    // ===== cross-attention =====
    ln_kernel<<<MX, 256>>>(x1, ln2_g, ln2_b, xn);
    run_gemm(false, xn, a2_wq, q, MX, INNER, Dd, Dd, INNER, INNER,
             0,0,0,0,0,0, 1, 1, 1.f, nullptr, nullptr, 0,0,0);
    // K2/V2 = context_flat[308,768] @ w[768,1024]
    run_gemm(false, ctx, a2_wk, k, Bb*CTX, INNER, CTXD, CTXD, INNER, INNER,
             0,0,0,0,0,0, 1, 1, 1.f, nullptr, nullptr, 0,0,0);
    run_gemm(false, ctx, a2_wv, v, Bb*CTX, INNER, CTXD, CTXD, INNER, INNER,
             0,0,0,0,0,0, 1, 1, 1.f, nullptr, nullptr, 0,0,0);
    // scores2[z=(b,h)]: M=S, N=CTX, K=DH
    run_gemm(true, q, k, sc, Ss, CTX, DH, INNER, INNER, CTX,
             (long)Ss*INNER, DH, (long)CTX*INNER, DH,
             (long)Hh*Ss*CTX, (long)Ss*CTX, Hh, Bb*Hh, scale,
             nullptr, nullptr, 0,0,0);
    softmax_kernel<<<(long)Bb*Hh*Ss, 128>>>(sc, CTX);
    // attn_out2: M=S, N=DH, K=CTX
    run_gemm(false, sc, v, ao, Ss, DH, CTX, CTX, INNER, INNER,
             (long)Hh*Ss*CTX, (long)Ss*CTX, (long)CTX*INNER, DH,
             (long)Ss*INNER, DH, Hh, Bb*Hh, 1.f,
             nullptr, nullptr, 0,0,0);
    // x1 = ao @ a2_wo + a2_bo + x1  (in-place residual: each elem read+written once)
    run_gemm(false, ao, a2_wo, x1, MX, Dd, INNER, INNER, Dd, Dd,
             0,0,0,0,0,0, 1, 1, 1.f, a2_bo, x1, 0,0, Dd);

    // ===== GeGLU feed-forward =====
    ln_kernel<<<MX, 256>>>(x1, ln3_g, ln3_b, xn);
    run_gemm(false, xn, ff_w1, ff, MX, FF2, Dd, Dd, FF2, FF2,
             0,0,0,0,0,0, 1, 1, 1.f, ff_b1, nullptr, 0,0,0);
    {
        long total = (long)MX * FF;
        int thr = 256;
        long blocks = (total + thr - 1) / thr;
        geglu_kernel<<<(unsigned)blocks, thr>>>(ff, gg);
    }
    // out = gg @ ff_w2 + ff_b2 + x1
    run_gemm(false, gg, ff_w2, out, MX, Dd, FF, FF, Dd, Dd,
             0,0,0,0,0,0, 1, 1, 1.f, ff_b2, x1, 0,0, Dd);
}

// round 5
// speedup vs baseline: 3.3054x; 3.3054x over previous
#include <cuda_runtime.h>
#include <cstdint>
#include <math.h>

// ================= problem constants =================
#define Bb 4
#define Ss 2048
#define Dd 1024
#define CTX 77
#define CTXP 80
#define CTXD 768
#define Hh 16
#define DH 64
#define INNER 1024
#define FF 4096
#define FF2 8192
#define MX (Bb*Ss)

// ================= scratch =================
__device__ float g_xn[MX * Dd];
__device__ float g_q [MX * INNER];
__device__ float g_k [MX * INNER];
__device__ float g_v [MX * INNER];
__device__ float g_ao[MX * INNER];
__device__ float g_x1[MX * Dd];
__device__ float g_sc[(long)Bb * Hh * Ss * Ss];
__device__ float g_ff[(long)MX * FF2];
__device__ float g_gg[(long)MX * FF];
__device__ float g_vt[(long)Bb * Hh * DH * Ss];
__device__ float g_cvt[(long)Bb * Hh * DH * CTXP];
__device__ float g_w1t[INNER * Dd];
__device__ float g_w2t[INNER * Dd];
__device__ float g_w3t[INNER * Dd];
__device__ float g_w4t[Dd * INNER];
__device__ float g_w5t[INNER * Dd];
__device__ float g_w6t[INNER * CTXD];
__device__ float g_w7t[INNER * CTXD];
__device__ float g_w8t[Dd * INNER];
__device__ float g_f1t[(long)FF2 * Dd];
__device__ float g_f2t[(long)Dd * FF];

// ================= tf32 helpers =================
__device__ __forceinline__ uint32_t f2tf32(float v) {
    uint32_t r;
    asm("cvt.rna.tf32.f32 %0, %1;" : "=r"(r) : "f"(v));
    return r;
}
__device__ __forceinline__ void mma_tf32(float c[4], const uint32_t a[4],
                                         uint32_t b0, uint32_t b1) {
    asm volatile(
        "mma.sync.aligned.m16n8k8.row.col.f32.tf32.tf32.f32 "
        "{%0,%1,%2,%3}, {%4,%5,%6,%7}, {%8,%9}, {%0,%1,%2,%3};"
        : "+f"(c[0]), "+f"(c[1]), "+f"(c[2]), "+f"(c[3])
        : "r"(a[0]), "r"(a[1]), "r"(a[2]), "r"(a[3]), "r"(b0), "r"(b1));
}

// ================= tf32 mma.sync GEMM =================
// C[m,n] = alpha*sum_k A[m,k]*B[n,k] (+bias[n]) (+res[m,n]); batched over blockIdx.z
// Block tile 128 x BN x 32. 8 warps (2m x 4n), warp tile 64 x BN/4.
// SMEM [row][Kpad=36]: fragment LDS bank = (4*row + k) mod 32 -> conflict-free.
#define KPAD 36

template<int BN, bool GUARD>
__global__ void __launch_bounds__(256)
mma_gemm(const float* __restrict__ A, const float* __restrict__ B, float* __restrict__ C,
         int M, int N, int K, int lda, int ldb, int ldc,
         long sAb, long sAh, long sBb, long sBh, long sCb, long sCh, int HH,
         float alpha, const float* __restrict__ bias,
         const float* __restrict__ res, long sRb, long sRh, int ldr) {
    __shared__ uint32_t As[128 * KPAD];
    __shared__ uint32_t Bs[BN * KPAD];

    constexpr int NFR = BN / 32;     // n-fragments per warp (warp n-tile = BN/4)
    constexpr int BJ  = BN / 32;     // float4 B chunks per thread
    constexpr int BSC = BN / 8;      // scalar B elems per thread (guard)

    int tid = threadIdx.x, lane = tid & 31, wid = tid >> 5;
    int g = lane >> 2, t = lane & 3;
    int z = blockIdx.z, zb = z / HH, zh = z % HH;
    A += zb * sAb + zh * sAh;
    B += zb * sBb + zh * sBh;
    C += zb * sCb + zh * sCh;
    if (res) res += zb * sRb + zh * sRh;
    int m0 = blockIdx.y * 128, n0 = blockIdx.x * BN;

    int wm = wid & 1, wn = wid >> 1;
    int mb = wm * 64, nb = wn * (BN / 4);

    float acc[4][NFR][4];
    #pragma unroll
    for (int i = 0; i < 4; i++)
        #pragma unroll
        for (int j = 0; j < NFR; j++)
            #pragma unroll
            for (int q = 0; q < 4; q++) acc[i][j][q] = 0.f;

    float4 ra[4], rb[BJ];
    float  sa[16], sb[BSC];

    int ns = (K + 31) >> 5;

    // ---- stage load (gmem -> regs) ----
    auto load_stage = [&](int s) {
        int k0 = s << 5;
        if (!GUARD) {
            #pragma unroll
            for (int j = 0; j < 4; j++) {
                int idx = tid + j * 256;
                int r = idx >> 3, c = idx & 7;
                ra[j] = *(const float4*)(A + (size_t)(m0 + r) * lda + k0 + c * 4);
            }
            #pragma unroll
            for (int j = 0; j < BJ; j++) {
                int idx = tid + j * 256;
                int r = idx >> 3, c = idx & 7;
                rb[j] = *(const float4*)(B + (size_t)(n0 + r) * ldb + k0 + c * 4);
            }
        } else {
            #pragma unroll
            for (int j = 0; j < 16; j++) {
                int idx = tid + j * 256;
                int r = idx >> 5, c = idx & 31;
                int gm = m0 + r, gk = k0 + c;
                sa[j] = (gm < M && gk < K) ? A[(size_t)gm * lda + gk] : 0.f;
            }
            #pragma unroll
            for (int j = 0; j < BSC; j++) {
                int idx = tid + j * 256;
                int r = idx >> 5, c = idx & 31;
                int gn = n0 + r, gk = k0 + c;
                sb[j] = (gn < N && gk < K) ? B[(size_t)gn * ldb + gk] : 0.f;
            }
        }
    };

    // ---- stage store (regs -> smem, with tf32 RN conversion) ----
    auto store_stage = [&]() {
        if (!GUARD) {
            #pragma unroll
            for (int j = 0; j < 4; j++) {
                int idx = tid + j * 256;
                int r = idx >> 3, c = idx & 7;
                uint4 u = { f2tf32(ra[j].x), f2tf32(ra[j].y), f2tf32(ra[j].z), f2tf32(ra[j].w) };
                *(uint4*)&As[r * KPAD + c * 4] = u;
            }
            #pragma unroll
            for (int j = 0; j < BJ; j++) {
                int idx = tid + j * 256;
                int r = idx >> 3, c = idx & 7;
                uint4 u = { f2tf32(rb[j].x), f2tf32(rb[j].y), f2tf32(rb[j].z), f2tf32(rb[j].w) };
                *(uint4*)&Bs[r * KPAD + c * 4] = u;
            }
        } else {
            #pragma unroll
            for (int j = 0; j < 16; j++) {
                int idx = tid + j * 256;
                int r = idx >> 5, c = idx & 31;
                As[r * KPAD + c] = f2tf32(sa[j]);
            }
            #pragma unroll
            for (int j = 0; j < BSC; j++) {
                int idx = tid + j * 256;
                int r = idx >> 5, c = idx & 31;
                Bs[r * KPAD + c] = f2tf32(sb[j]);
            }
        }
    };

    load_stage(0);
    for (int s = 0; s < ns; s++) {
        if (s > 0) __syncthreads();
        store_stage();
        __syncthreads();
        if (s + 1 < ns) load_stage(s + 1);

        #pragma unroll
        for (int k8 = 0; k8 < 4; k8++) {
            int kk = k8 * 8;
            uint32_t a[4][4];
            #pragma unroll
            for (int i = 0; i < 4; i++) {
                int m = mb + i * 16 + g;
                a[i][0] = As[m * KPAD + kk + t];
                a[i][1] = As[(m + 8) * KPAD + kk + t];
                a[i][2] = As[m * KPAD + kk + t + 4];
                a[i][3] = As[(m + 8) * KPAD + kk + t + 4];
            }
            #pragma unroll
            for (int j = 0; j < NFR; j++) {
                int n = nb + j * 8 + g;
                uint32_t b0 = Bs[n * KPAD + kk + t];
                uint32_t b1 = Bs[n * KPAD + kk + t + 4];
                #pragma unroll
                for (int i = 0; i < 4; i++) mma_tf32(acc[i][j], a[i], b0, b1);
            }
        }
    }

    // ---- epilogue ----
    #pragma unroll
    for (int i = 0; i < 4; i++) {
        int gm = m0 + mb + i * 16 + g;
        #pragma unroll
        for (int j = 0; j < NFR; j++) {
            int gn = n0 + nb + j * 8 + 2 * t;
            float v0 = acc[i][j][0] * alpha, v1 = acc[i][j][1] * alpha;
            float v2 = acc[i][j][2] * alpha, v3 = acc[i][j][3] * alpha;
            if (!GUARD) {
                if (bias) {
                    float b0 = bias[gn], b1 = bias[gn + 1];
                    v0 += b0; v1 += b1; v2 += b0; v3 += b1;
                }
                if (res) {
                    float2 r0 = *(const float2*)&res[(size_t)gm * ldr + gn];
                    float2 r1 = *(const float2*)&res[(size_t)(gm + 8) * ldr + gn];
                    v0 += r0.x; v1 += r0.y; v2 += r1.x; v3 += r1.y;
                }
                *(float2*)&C[(size_t)gm * ldc + gn]       = make_float2(v0, v1);
                *(float2*)&C[(size_t)(gm + 8) * ldc + gn] = make_float2(v2, v3);
            } else {
                if (gm < M) {
                    if (gn < N) {
                        float v = v0;
                        if (bias) v += bias[gn];
                        if (res)  v += res[(size_t)gm * ldr + gn];
                        C[(size_t)gm * ldc + gn] = v;
                    }
                    if (gn + 1 < N) {
                        float v = v1;
                        if (bias) v += bias[gn + 1];
                        if (res)  v += res[(size_t)gm * ldr + gn + 1];
                        C[(size_t)gm * ldc + gn + 1] = v;
                    }
                }
                if (gm + 8 < M) {
                    if (gn < N) {
                        float v = v2;
                        if (bias) v += bias[gn];
                        if (res)  v += res[(size_t)(gm + 8) * ldr + gn];
                        C[(size_t)(gm + 8) * ldc + gn] = v;
                    }
                    if (gn + 1 < N) {
                        float v = v3;
                        if (bias) v += bias[gn + 1];
                        if (res)  v += res[(size_t)(gm + 8) * ldr + gn + 1];
                        C[(size_t)(gm + 8) * ldc + gn + 1] = v;
                    }
                }
            }
        }
    }
}

// ================= reductions =================
__device__ __forceinline__ float warp_sum(float v) {
    #pragma unroll
    for (int o = 16; o > 0; o >>= 1) v += __shfl_xor_sync(0xffffffffu, v, o);
    return v;
}
__device__ __forceinline__ float warp_max(float v) {
    #pragma unroll
    for (int o = 16; o > 0; o >>= 1) v = fmaxf(v, __shfl_xor_sync(0xffffffffu, v, o));
    return v;
}

// ================= layernorm =================
__global__ void ln_kernel(const float* __restrict__ x, const float* __restrict__ g,
                          const float* __restrict__ b, float* __restrict__ y) {
    size_t row = blockIdx.x;
    const float* xr = x + row * Dd;
    float s = 0.f, s2 = 0.f;
    for (int i = threadIdx.x; i < Dd; i += blockDim.x) {
        float v = xr[i];
        s += v; s2 += v * v;
    }
    __shared__ float sm1[32], sm2[32];
    s = warp_sum(s); s2 = warp_sum(s2);
    int lane = threadIdx.x & 31, w = threadIdx.x >> 5;
    if (lane == 0) { sm1[w] = s; sm2[w] = s2; }
    __syncthreads();
    int nw = blockDim.x >> 5;
    if (w == 0) {
        float a = (lane < nw) ? sm1[lane] : 0.f;
        float c = (lane < nw) ? sm2[lane] : 0.f;
        a = warp_sum(a); c = warp_sum(c);
        if (lane == 0) { sm1[0] = a; sm2[0] = c; }
    }
    __syncthreads();
    float mu = sm1[0] * (1.f / Dd);
    float var = sm2[0] * (1.f / Dd) - mu * mu;
    float inv = rsqrtf(var + 1e-5f);
    float* yr = y + row * Dd;
    for (int i = threadIdx.x; i < Dd; i += blockDim.x)
        yr[i] = (xr[i] - mu) * inv * g[i] + b[i];
}

// ================= softmax L=2048 =================
__global__ void softmax2048(float* __restrict__ p) {
    size_t row = blockIdx.x;
    float* r = p + row * (size_t)Ss;
    int tid = threadIdx.x;
    float v[8];
    #pragma unroll
    for (int i = 0; i < 8; i++) v[i] = r[tid + i * 256];
    float mx = v[0];
    #pragma unroll
    for (int i = 1; i < 8; i++) mx = fmaxf(mx, v[i]);
    __shared__ float sm[32];
    mx = warp_max(mx);
    int lane = tid & 31, w = tid >> 5;
    if (lane == 0) sm[w] = mx;
    __syncthreads();
    if (w == 0) {
        float t2 = (lane < 8) ? sm[lane] : -INFINITY;
        t2 = warp_max(t2);
        if (lane == 0) sm[0] = t2;
    }
    __syncthreads();
    mx = sm[0];
    __syncthreads();
    float s = 0.f;
    #pragma unroll
    for (int i = 0; i < 8; i++) { v[i] = __expf(v[i] - mx); s += v[i]; }
    s = warp_sum(s);
    if (lane == 0) sm[w] = s;
    __syncthreads();
    if (w == 0) {
        float t2 = (lane < 8) ? sm[lane] : 0.f;
        t2 = warp_sum(t2);
        if (lane == 0) sm[0] = t2;
    }
    __syncthreads();
    float inv = 1.f / sm[0];
    #pragma unroll
    for (int i = 0; i < 8; i++) r[tid + i * 256] = v[i] * inv;
}

// ================= softmax L=77 (ld=80) =================
__global__ void softmax77(float* __restrict__ p) {
    int wid = threadIdx.x >> 5, lane = threadIdx.x & 31;
    size_t row = (size_t)blockIdx.x * 4 + wid;
    float* r = p + row * CTXP;
    float v0 = (lane < CTX)      ? r[lane]      : -INFINITY;
    float v1 = (lane + 32 < CTX) ? r[lane + 32] : -INFINITY;
    float v2 = (lane + 64 < CTX) ? r[lane + 64] : -INFINITY;
    float mx = warp_max(fmaxf(v0, fmaxf(v1, v2)));
    v0 = (lane < CTX)      ? __expf(v0 - mx) : 0.f;
    v1 = (lane + 32 < CTX) ? __expf(v1 - mx) : 0.f;
    v2 = (lane + 64 < CTX) ? __expf(v2 - mx) : 0.f;
    float s = warp_sum(v0 + v1 + v2);
    float inv = 1.f / s;
    if (lane < CTX)      r[lane]      = v0 * inv;
    if (lane + 32 < CTX) r[lane + 32] = v1 * inv;
    if (lane + 64 < CTX) r[lane + 64] = v2 * inv;
}

// ================= GeGLU =================
__global__ void geglu_kernel(const float* __restrict__ h, float* __restrict__ o) {
    size_t idx = (size_t)blockIdx.x * blockDim.x + threadIdx.x;
    size_t m = idx >> 12;
    int n = (int)(idx & (FF - 1));
    float u    = h[m * FF2 + n];
    float gate = h[m * FF2 + FF + n];
    float ge = 0.5f * gate * (1.f + erff(gate * 0.70710678118654752f));
    o[idx] = u * ge;
}

// ================= batched transpose =================
__global__ void transpose_kernel(const float* __restrict__ in, float* __restrict__ out,
                                 int R, int C, int ldin, int ldout,
                                 long sInB, long sInH, long sOutB, long sOutH, int HH) {
    __shared__ float t[32][33];
    int z = blockIdx.z, zb = z / HH, zh = z % HH;
    in += zb * sInB + zh * sInH;
    out += zb * sOutB + zh * sOutH;
    int c = blockIdx.x * 32 + threadIdx.x;
    #pragma unroll
    for (int j = 0; j < 4; j++) {
        int r = blockIdx.y * 32 + threadIdx.y + j * 8;
        if (r < R && c < C) t[threadIdx.y + j * 8][threadIdx.x] = in[(size_t)r * ldin + c];
    }
    __syncthreads();
    int rr = blockIdx.y * 32 + threadIdx.x;
    #pragma unroll
    for (int j = 0; j < 4; j++) {
        int cc = blockIdx.x * 32 + threadIdx.y + j * 8;
        if (cc < C && rr < R) out[(size_t)cc * ldout + rr] = t[threadIdx.x][threadIdx.y + j * 8];
    }
}

// ================= host wrappers =================
static void run_mma(int BN, bool guard, const float* A, const float* B, float* C,
                    int M, int N, int K, int lda, int ldb, int ldc,
                    long sAb, long sAh, long sBb, long sBh, long sCb, long sCh,
                    int HH, int Z, float alpha,
                    const float* bias, const float* res, long sRb, long sRh, int ldr) {
    dim3 grid((N + BN - 1) / BN, (M + 127) / 128, Z);
    if (BN == 128) {
        if (guard) mma_gemm<128, true ><<<grid, 256>>>(A, B, C, M, N, K, lda, ldb, ldc,
                    sAb, sAh, sBb, sBh, sCb, sCh, HH, alpha, bias, res, sRb, sRh, ldr);
        else       mma_gemm<128, false><<<grid, 256>>>(A, B, C, M, N, K, lda, ldb, ldc,
                    sAb, sAh, sBb, sBh, sCb, sCh, HH, alpha, bias, res, sRb, sRh, ldr);
    } else {
        if (guard) mma_gemm<64, true ><<<grid, 256>>>(A, B, C, M, N, K, lda, ldb, ldc,
                    sAb, sAh, sBb, sBh, sCb, sCh, HH, alpha, bias, res, sRb, sRh, ldr);
        else       mma_gemm<64, false><<<grid, 256>>>(A, B, C, M, N, K, lda, ldb, ldc,
                    sAb, sAh, sBb, sBh, sCb, sCh, HH, alpha, bias, res, sRb, sRh, ldr);
    }
}

static void run_tr(const float* in, float* out, int R, int C, int ldin, int ldout,
                   long sInB, long sInH, long sOutB, long sOutH, int HH, int Z) {
    dim3 grid((C + 31) / 32, (R + 31) / 32, Z);
    transpose_kernel<<<grid, dim3(32, 8)>>>(in, out, R, C, ldin, ldout,
                                            sInB, sInH, sOutB, sOutH, HH);
}

extern "C" void kernel_launch(void* const* d_in, const int* in_sizes, int n_in,
                              void* d_out, int out_size) {
    const float* x      = (const float*)d_in[0];
    const float* ctx    = (const float*)d_in[1];
    const float* ln1_g  = (const float*)d_in[2];
    const float* ln1_b  = (const float*)d_in[3];
    const float* ln2_g  = (const float*)d_in[4];
    const float* ln2_b  = (const float*)d_in[5];
    const float* ln3_g  = (const float*)d_in[6];
    const float* ln3_b  = (const float*)d_in[7];
    const float* a1_wq  = (const float*)d_in[8];
    const float* a1_wk  = (const float*)d_in[9];
    const float* a1_wv  = (const float*)d_in[10];
    const float* a1_wo  = (const float*)d_in[11];
    const float* a1_bo  = (const float*)d_in[12];
    const float* a2_wq  = (const float*)d_in[13];
    const float* a2_wk  = (const float*)d_in[14];
    const float* a2_wv  = (const float*)d_in[15];
    const float* a2_wo  = (const float*)d_in[16];
    const float* a2_bo  = (const float*)d_in[17];
    const float* ff_w1  = (const float*)d_in[18];
    const float* ff_b1  = (const float*)d_in[19];
    const float* ff_w2  = (const float*)d_in[20];
    const float* ff_b2  = (const float*)d_in[21];
    float* out = (float*)d_out;

    float *xn, *q, *k, *v, *ao, *x1, *sc, *ff, *gg, *vt, *cvt;
    float *w1t, *w2t, *w3t, *w4t, *w5t, *w6t, *w7t, *w8t, *f1t, *f2t;
    cudaGetSymbolAddress((void**)&xn, g_xn);
    cudaGetSymbolAddress((void**)&q,  g_q);
    cudaGetSymbolAddress((void**)&k,  g_k);
    cudaGetSymbolAddress((void**)&v,  g_v);
    cudaGetSymbolAddress((void**)&ao, g_ao);
    cudaGetSymbolAddress((void**)&x1, g_x1);
    cudaGetSymbolAddress((void**)&sc, g_sc);
    cudaGetSymbolAddress((void**)&ff, g_ff);
    cudaGetSymbolAddress((void**)&gg, g_gg);
    cudaGetSymbolAddress((void**)&vt, g_vt);
    cudaGetSymbolAddress((void**)&cvt, g_cvt);
    cudaGetSymbolAddress((void**)&w1t, g_w1t);
    cudaGetSymbolAddress((void**)&w2t, g_w2t);
    cudaGetSymbolAddress((void**)&w3t, g_w3t);
    cudaGetSymbolAddress((void**)&w4t, g_w4t);
    cudaGetSymbolAddress((void**)&w5t, g_w5t);
    cudaGetSymbolAddress((void**)&w6t, g_w6t);
    cudaGetSymbolAddress((void**)&w7t, g_w7t);
    cudaGetSymbolAddress((void**)&w8t, g_w8t);
    cudaGetSymbolAddress((void**)&f1t, g_f1t);
    cudaGetSymbolAddress((void**)&f2t, g_f2t);

    const float scale = 0.125f;

    // ---- weight transposes (W[K,N] -> Wt[N,K]) ----
    run_tr(a1_wq, w1t, Dd, INNER, INNER, Dd, 0,0,0,0, 1, 1);
    run_tr(a1_wk, w2t, Dd, INNER, INNER, Dd, 0,0,0,0, 1, 1);
    run_tr(a1_wv, w3t, Dd, INNER, INNER, Dd, 0,0,0,0, 1, 1);
    run_tr(a1_wo, w4t, INNER, Dd, Dd, INNER, 0,0,0,0, 1, 1);
    run_tr(a2_wq, w5t, Dd, INNER, INNER, Dd, 0,0,0,0, 1, 1);
    run_tr(a2_wk, w6t, CTXD, INNER, INNER, CTXD, 0,0,0,0, 1, 1);
    run_tr(a2_wv, w7t, CTXD, INNER, INNER, CTXD, 0,0,0,0, 1, 1);
    run_tr(a2_wo, w8t, INNER, Dd, Dd, INNER, 0,0,0,0, 1, 1);
    run_tr(ff_w1, f1t, Dd, FF2, FF2, Dd, 0,0,0,0, 1, 1);
    run_tr(ff_w2, f2t, FF, Dd, Dd, FF, 0,0,0,0, 1, 1);

    // ===== self-attention =====
    ln_kernel<<<MX, 256>>>(x, ln1_g, ln1_b, xn);
    run_mma(128, false, xn, w1t, q, MX, INNER, Dd, Dd, Dd, INNER,
            0,0,0,0,0,0, 1, 1, 1.f, nullptr, nullptr, 0,0,0);
    run_mma(128, false, xn, w2t, k, MX, INNER, Dd, Dd, Dd, INNER,
            0,0,0,0,0,0, 1, 1, 1.f, nullptr, nullptr, 0,0,0);
    run_mma(128, false, xn, w3t, v, MX, INNER, Dd, Dd, Dd, INNER,
            0,0,0,0,0,0, 1, 1, 1.f, nullptr, nullptr, 0,0,0);
    run_tr(v, vt, Ss, DH, INNER, Ss,
           (long)Ss * INNER, DH, (long)Hh * DH * Ss, (long)DH * Ss, Hh, Bb * Hh);
    // scores = Q @ K^T * scale (M=S, N=S, K=64)
    run_mma(128, false, q, k, sc, Ss, Ss, DH, INNER, INNER, Ss,
            (long)Ss * INNER, DH, (long)Ss * INNER, DH,
            (long)Hh * Ss * Ss, (long)Ss * Ss, Hh, Bb * Hh, scale, nullptr, nullptr, 0,0,0);
    softmax2048<<<(unsigned)((size_t)Bb * Hh * Ss), 256>>>(sc);
    // ao = P @ V (M=S, N=64 exact, K=S)
    run_mma(64, false, sc, vt, ao, Ss, DH, Ss, Ss, Ss, INNER,
            (long)Hh * Ss * Ss, (long)Ss * Ss, (long)Hh * DH * Ss, (long)DH * Ss,
            (long)Ss * INNER, DH, Hh, Bb * Hh, 1.f, nullptr, nullptr, 0,0,0);
    // x1 = ao @ woT + bo + x
    run_mma(128, false, ao, w4t, x1, MX, Dd, INNER, INNER, INNER, Dd,
            0,0,0,0,0,0, 1, 1, 1.f, a1_bo, x, 0,0, Dd);

    // ===== cross-attention =====
    ln_kernel<<<MX, 256>>>(x1, ln2_g, ln2_b, xn);
    run_mma(128, false, xn, w5t, q, MX, INNER, Dd, Dd, Dd, INNER,
            0,0,0,0,0,0, 1, 1, 1.f, nullptr, nullptr, 0,0,0);
    run_mma(128, true, ctx, w6t, k, Bb * CTX, INNER, CTXD, CTXD, CTXD, INNER,
            0,0,0,0,0,0, 1, 1, 1.f, nullptr, nullptr, 0,0,0);
    run_mma(128, true, ctx, w7t, v, Bb * CTX, INNER, CTXD, CTXD, CTXD, INNER,
            0,0,0,0,0,0, 1, 1, 1.f, nullptr, nullptr, 0,0,0);
    run_tr(v, cvt, CTX, DH, INNER, CTXP,
           (long)CTX * INNER, DH, (long)Hh * DH * CTXP, (long)DH * CTXP, Hh, Bb * Hh);
    // cross scores (N=77, K=64), C ld=80
    run_mma(128, true, q, k, sc, Ss, CTX, DH, INNER, INNER, CTXP,
            (long)Ss * INNER, DH, (long)CTX * INNER, DH,
            (long)Hh * Ss * CTXP, (long)Ss * CTXP, Hh, Bb * Hh, scale, nullptr, nullptr, 0,0,0);
    softmax77<<<(unsigned)((size_t)Bb * Hh * Ss / 4), 128>>>(sc);
    // cross PV (N=64, K=77)
    run_mma(64, true, sc, cvt, ao, Ss, DH, CTX, CTXP, CTXP, INNER,
            (long)Hh * Ss * CTXP, (long)Ss * CTXP, (long)Hh * DH * CTXP, (long)DH * CTXP,
            (long)Ss * INNER, DH, Hh, Bb * Hh, 1.f, nullptr, nullptr, 0,0,0);
    run_mma(128, false, ao, w8t, x1, MX, Dd, INNER, INNER, INNER, Dd,
            0,0,0,0,0,0, 1, 1, 1.f, a2_bo, x1, 0,0, Dd);

    // ===== GeGLU feed-forward =====
    ln_kernel<<<MX, 256>>>(x1, ln3_g, ln3_b, xn);
    run_mma(128, false, xn, f1t, ff, MX, FF2, Dd, Dd, Dd, FF2,
            0,0,0,0,0,0, 1, 1, 1.f, ff_b1, nullptr, 0,0,0);
    {
        size_t total = (size_t)MX * FF;
        geglu_kernel<<<(unsigned)(total / 256), 256>>>(ff, gg);
    }
    run_mma(128, false, gg, f2t, out, MX, Dd, FF, FF, FF, Dd,
            0,0,0,0,0,0, 1, 1, 1.f, ff_b2, x1, 0,0, Dd);
}